// round 13
// baseline (speedup 1.0000x reference)
#include <cuda_runtime.h>
#include <cstddef>

#define NUC 100000
#define NIC 50000
#define DC 64
#define EBC 500000
#define ECC 1000000
#define EPC 2000000
#define ETOT (EBC + ECC + EPC)
#define WPB 8     // warps per block
#define NPW 8     // nodes per warp (matmul register-blocking factor)

// ---------------- scratch (device globals; no allocation allowed) ----------
__device__ float g_srcB[NUC * DC];
__device__ float g_dstB[NIC * DC];
__device__ float g_se[3][NUC * DC];   // layer-0 (sum_e w) @ We, u-side
__device__ float g_de[3][NIC * DC];   // layer-0 (sum_e w) @ We, v-side
__device__ int g_cntU[3 * NUC];
__device__ int g_cntV[3 * NIC];
__device__ int g_rowU[3 * (NUC + 1)];
__device__ int g_rowV[3 * (NIC + 1)];
__device__ int g_curU[3 * NUC];
__device__ int g_curV[3 * NIC];
__device__ float2 g_drU[3 * NUC];     // {deg, rsqrt(deg)}
__device__ float2 g_drV[3 * NIC];
__device__ int2 g_adjU[ETOT];         // {edge id, opposite node}
__device__ int2 g_adjV[ETOT];

__device__ __forceinline__ float lk(float x) { return x >= 0.f ? x : 0.01f * x; }

// ---------------- setup kernels --------------------------------------------

__global__ void k_init(const float4* __restrict__ in, float s,
                       float4* __restrict__ out, int n4) {
    int i = blockIdx.x * blockDim.x + threadIdx.x;
    if (i < n4) {
        float4 v = in[i];
        out[i] = make_float4(v.x * s, v.y * s, v.z * s, v.w * s);
    }
}

__global__ void k_hist(const int* __restrict__ U, const int* __restrict__ V, int E,
                       int* __restrict__ cU, int* __restrict__ cV) {
    int i = blockIdx.x * blockDim.x + threadIdx.x;
    if (i < E) {
        atomicAdd(cU + U[i], 1);
        atomicAdd(cV + V[i], 1);
    }
}

__global__ void k_deg(const int* __restrict__ cnt, float2* __restrict__ dr, int n) {
    int i = blockIdx.x * blockDim.x + threadIdx.x;
    if (i < n) {
        float d = (float)(cnt[i] < 1 ? 1 : cnt[i]);
        dr[i] = make_float2(d, rsqrtf(d));
    }
}

__global__ void k_scan6(const int* __restrict__ cntU, const int* __restrict__ cntV,
                        int* __restrict__ rowU, int* __restrict__ rowV,
                        int* __restrict__ curU, int* __restrict__ curV) {
    __shared__ int ssum[1024];
    int b = blockIdx.x, side = b / 3, t = b % 3;
    const int* cnt; int* row; int* cur; int n;
    if (side == 0) { n = NUC; cnt = cntU + t * NUC; row = rowU + t * (NUC + 1); cur = curU + t * NUC; }
    else           { n = NIC; cnt = cntV + t * NIC; row = rowV + t * (NIC + 1); cur = curV + t * NIC; }
    int tid = threadIdx.x;
    int chunk = (n + 1023) / 1024;
    int lo = tid * chunk; if (lo > n) lo = n;
    int hi = lo + chunk; if (hi > n) hi = n;
    int s = 0;
    for (int i = lo; i < hi; i++) s += cnt[i];
    ssum[tid] = s;
    __syncthreads();
    for (int off = 1; off < 1024; off <<= 1) {
        int v = (tid >= off) ? ssum[tid - off] : 0;
        __syncthreads();
        ssum[tid] += v;
        __syncthreads();
    }
    int run = (tid == 0) ? 0 : ssum[tid - 1];
    for (int i = lo; i < hi; i++) {
        row[i] = run; cur[i] = run;
        run += cnt[i];
    }
    if (hi == n) row[n] = run;
}

__global__ void k_fill(const int* __restrict__ U, const int* __restrict__ V, int E,
                       int* __restrict__ cU, int* __restrict__ cV,
                       int2* __restrict__ adjU, int2* __restrict__ adjV) {
    int e = blockIdx.x * blockDim.x + threadIdx.x;
    if (e < E) {
        int u = U[e], v = V[e];
        int pu = atomicAdd(cU + u, 1);
        adjU[pu] = make_int2(e, v);
        int pv = atomicAdd(cV + v, 1);
        adjV[pv] = make_int2(e, u);
    }
}

// ---------------- layer 0 ----------------------------------------------------
// One edge per warp, float2 lanes, batch-8 MLP. Rows staged to (dynamic) smem;
// after 8 nodes, one register-blocked dual matmul (a@Wn, b@We) re-uses each
// weight load 8x. Dynamic smem: 64KB (exceeds 48KB static limit).
__global__ void __launch_bounds__(WPB * 32) k_l0(
        const float* __restrict__ e0, const float* __restrict__ e1,
        const float* __restrict__ e2,
        const int2* __restrict__ adjAll, const int* __restrict__ rowAll,
        int rowStride,
        const float* __restrict__ oppEmb, float oppScale,
        const float2* __restrict__ drOppAll, int nOpp,
        const float2* __restrict__ drMyAll,
        const float* __restrict__ Wn, const float* __restrict__ We,
        float* __restrict__ nxt, float* __restrict__ seOut,
        float* __restrict__ outp, int n) {
    int t = blockIdx.y;
    const float* ew = (t == 0) ? e0 : (t == 1 ? e1 : e2);
    size_t eoff = (t > 0 ? (size_t)EBC : 0) + (t > 1 ? (size_t)ECC : 0);
    const int2* adj = adjAll + eoff;
    const int* row = rowAll + t * rowStride;
    const float2* drOpp = drOppAll + t * nOpp;
    const float2* drMy = drMyAll + t * n;
    float* se = seOut + (size_t)t * n * DC;
    float wgt = (t == 0) ? 1.f : (t == 1 ? 0.5f : 0.25f);
    const float Bsc = 0.0045f;

    extern __shared__ float smemPool[];
    float2* sWn2 = (float2*)smemPool;                    // 2048 float2 = 16KB
    float2* sWe2 = sWn2 + 2048;                          // 16KB
    float*  rowA = (float*)(sWe2 + 2048);                // WPB*NPW*DC = 16KB
    float*  rowB = rowA + WPB * NPW * DC;                // 16KB

    int tid = threadIdx.x;
    for (int i = tid; i < 2048; i += WPB * 32) {
        sWn2[i] = ((const float2*)Wn)[i];
        sWe2[i] = ((const float2*)We)[i];
    }
    __syncthreads();

    int wid = tid >> 5, lane = tid & 31;
    float* myRowA = rowA + wid * NPW * DC;
    float* myRowB = rowB + wid * NPW * DC;
    int nodeBase = (blockIdx.x * WPB + wid) * NPW;
    if (nodeBase >= n) return;

    // ---- gather phase: one node at a time, one edge per warp, batch 8 ----
    for (int nd = 0; nd < NPW; nd++) {
        int node = nodeBase + nd;
        float2 a = make_float2(0.f, 0.f);
        float2 b = make_float2(0.f, 0.f);
        if (node < n) {
            int i = row[node], s1 = row[node + 1];
            for (; i + 7 < s1; i += 8) {
                int2 ad[8];
#pragma unroll
                for (int j = 0; j < 8; j++) ad[j] = __ldg(adj + i + j);
                float2 w2[8], f2[8];
                float r[8];
#pragma unroll
                for (int j = 0; j < 8; j++) r[j] = __ldg(drOpp + ad[j].y).y * oppScale;
#pragma unroll
                for (int j = 0; j < 8; j++) w2[j] = __ldg((const float2*)(ew + (size_t)ad[j].x * DC) + lane);
#pragma unroll
                for (int j = 0; j < 8; j++) f2[j] = __ldg((const float2*)(oppEmb + (size_t)ad[j].y * DC) + lane);
#pragma unroll
                for (int j = 0; j < 8; j++) {
                    float wx = w2[j].x * Bsc, wy = w2[j].y * Bsc;
                    b.x += wx; b.y += wy;
                    a.x += f2[j].x * r[j] * wx;
                    a.y += f2[j].y * r[j] * wy;
                }
            }
            for (; i + 3 < s1; i += 4) {
                int2 ad[4];
#pragma unroll
                for (int j = 0; j < 4; j++) ad[j] = __ldg(adj + i + j);
                float2 w2[4], f2[4];
                float r[4];
#pragma unroll
                for (int j = 0; j < 4; j++) r[j] = __ldg(drOpp + ad[j].y).y * oppScale;
#pragma unroll
                for (int j = 0; j < 4; j++) w2[j] = __ldg((const float2*)(ew + (size_t)ad[j].x * DC) + lane);
#pragma unroll
                for (int j = 0; j < 4; j++) f2[j] = __ldg((const float2*)(oppEmb + (size_t)ad[j].y * DC) + lane);
#pragma unroll
                for (int j = 0; j < 4; j++) {
                    float wx = w2[j].x * Bsc, wy = w2[j].y * Bsc;
                    b.x += wx; b.y += wy;
                    a.x += f2[j].x * r[j] * wx;
                    a.y += f2[j].y * r[j] * wy;
                }
            }
            for (; i < s1; i++) {
                int2 ad = __ldg(adj + i);
                float rr = __ldg(drOpp + ad.y).y * oppScale;
                float2 w2 = __ldg((const float2*)(ew + (size_t)ad.x * DC) + lane);
                float2 f2 = __ldg((const float2*)(oppEmb + (size_t)ad.y * DC) + lane);
                float wx = w2.x * Bsc, wy = w2.y * Bsc;
                b.x += wx; b.y += wy;
                a.x += f2.x * rr * wx;
                a.y += f2.y * rr * wy;
            }
        }
        ((float2*)(myRowA + nd * DC))[lane] = a;
        ((float2*)(myRowB + nd * DC))[lane] = b;
    }
    __syncwarp();

    // ---- blocked dual matmul: 8 rows share each weight load ----
    float2 accn[NPW], acce[NPW];
#pragma unroll
    for (int r = 0; r < NPW; r++) {
        accn[r] = make_float2(0.f, 0.f);
        acce[r] = make_float2(0.f, 0.f);
    }
#pragma unroll 4
    for (int d2 = 0; d2 < 32; d2++) {
        float2 wn0 = sWn2[(2 * d2) * 32 + lane];
        float2 wn1 = sWn2[(2 * d2 + 1) * 32 + lane];
        float2 we0 = sWe2[(2 * d2) * 32 + lane];
        float2 we1 = sWe2[(2 * d2 + 1) * 32 + lane];
#pragma unroll
        for (int r = 0; r < NPW; r++) {
            float2 sa = ((const float2*)(myRowA + r * DC))[d2];
            float2 sb = ((const float2*)(myRowB + r * DC))[d2];
            accn[r].x += sa.x * wn0.x + sa.y * wn1.x;
            accn[r].y += sa.x * wn0.y + sa.y * wn1.y;
            acce[r].x += sb.x * we0.x + sb.y * we1.x;
            acce[r].y += sb.x * we0.y + sb.y * we1.y;
        }
    }

    // ---- epilogue ----
#pragma unroll
    for (int nd = 0; nd < NPW; nd++) {
        int node = nodeBase + nd;
        if (node >= n) break;
        float rsn = drMy[node].y;
        float2 res;
        res.x = lk(accn[nd].x * rsn) * wgt;
        res.y = lk(accn[nd].y * rsn) * wgt;
        size_t off = (size_t)node * DC + lane * 2;
        atomicAdd((float2*)(nxt + off), res);
        atomicAdd((float2*)(outp + off),
                  make_float2(res.x * (1.f / 3.f), res.y * (1.f / 3.f)));
        ((float2*)(se + (size_t)node * DC))[lane] = acce[nd];
    }
}

// ---------------- layer 1 ----------------------------------------------------
// w_e = leaky((seW[my] + deW[opp]) / (deg[my] + deg[opp])); agg = sum f*r*w.
// Same structure: float2 lanes, batch-8 gather, 8-row blocked matmul.
// Static smem: 16KB weights + 16KB rows = 32KB (within static limit).
__global__ void __launch_bounds__(WPB * 32) k_l1(
        const int2* __restrict__ adjAll, const int* __restrict__ rowAll,
        int rowStride,
        const float* __restrict__ myDeWAll, const float* __restrict__ oppDeWAll,
        const float2* __restrict__ drMyAll, const float2* __restrict__ drOppAll,
        const float* __restrict__ oppF, int nOpp,
        const float* __restrict__ Wn, float* __restrict__ outp, int n) {
    int t = blockIdx.y;
    size_t eoff = (t > 0 ? (size_t)EBC : 0) + (t > 1 ? (size_t)ECC : 0);
    const int2* adj = adjAll + eoff;
    const int* row = rowAll + t * rowStride;
    const float* myDeW = myDeWAll + (size_t)t * n * DC;
    const float* oppDeW = oppDeWAll + (size_t)t * nOpp * DC;
    const float2* drMy = drMyAll + t * n;
    const float2* drOpp = drOppAll + t * nOpp;
    float wgt = (t == 0) ? 1.f : (t == 1 ? 0.5f : 0.25f);

    __shared__ float2 sWn2[64 * 32];
    __shared__ float rowA[WPB][NPW][DC];

    int tid = threadIdx.x;
    for (int i = tid; i < 2048; i += WPB * 32) sWn2[i] = ((const float2*)Wn)[i];
    __syncthreads();

    int wid = tid >> 5, lane = tid & 31;
    int nodeBase = (blockIdx.x * WPB + wid) * NPW;
    if (nodeBase >= n) return;

    for (int nd = 0; nd < NPW; nd++) {
        int node = nodeBase + nd;
        float2 a = make_float2(0.f, 0.f);
        if (node < n) {
            float md = drMy[node].x;
            float2 m = __ldg((const float2*)(myDeW + (size_t)node * DC) + lane);
            int i = row[node], s1 = row[node + 1];
            for (; i + 7 < s1; i += 8) {
                int2 ad[8];
#pragma unroll
                for (int j = 0; j < 8; j++) ad[j] = __ldg(adj + i + j);
                float2 dr[8], o2[8], f2[8];
#pragma unroll
                for (int j = 0; j < 8; j++) dr[j] = __ldg(drOpp + ad[j].y);
#pragma unroll
                for (int j = 0; j < 8; j++) o2[j] = __ldg((const float2*)(oppDeW + (size_t)ad[j].y * DC) + lane);
#pragma unroll
                for (int j = 0; j < 8; j++) f2[j] = __ldg((const float2*)(oppF + (size_t)ad[j].y * DC) + lane);
#pragma unroll
                for (int j = 0; j < 8; j++) {
                    float s = 1.f / (md + dr[j].x);
                    float r = dr[j].y;
                    a.x += f2[j].x * r * lk((m.x + o2[j].x) * s);
                    a.y += f2[j].y * r * lk((m.y + o2[j].y) * s);
                }
            }
            for (; i + 3 < s1; i += 4) {
                int2 ad[4];
#pragma unroll
                for (int j = 0; j < 4; j++) ad[j] = __ldg(adj + i + j);
                float2 dr[4], o2[4], f2[4];
#pragma unroll
                for (int j = 0; j < 4; j++) dr[j] = __ldg(drOpp + ad[j].y);
#pragma unroll
                for (int j = 0; j < 4; j++) o2[j] = __ldg((const float2*)(oppDeW + (size_t)ad[j].y * DC) + lane);
#pragma unroll
                for (int j = 0; j < 4; j++) f2[j] = __ldg((const float2*)(oppF + (size_t)ad[j].y * DC) + lane);
#pragma unroll
                for (int j = 0; j < 4; j++) {
                    float s = 1.f / (md + dr[j].x);
                    float r = dr[j].y;
                    a.x += f2[j].x * r * lk((m.x + o2[j].x) * s);
                    a.y += f2[j].y * r * lk((m.y + o2[j].y) * s);
                }
            }
            for (; i < s1; i++) {
                int2 ad = __ldg(adj + i);
                float2 dro = __ldg(drOpp + ad.y);
                float s = 1.f / (md + dro.x);
                float r = dro.y;
                float2 o2 = __ldg((const float2*)(oppDeW + (size_t)ad.y * DC) + lane);
                float2 f2 = __ldg((const float2*)(oppF + (size_t)ad.y * DC) + lane);
                a.x += f2.x * r * lk((m.x + o2.x) * s);
                a.y += f2.y * r * lk((m.y + o2.y) * s);
            }
        }
        ((float2*)rowA[wid][nd])[lane] = a;
    }
    __syncwarp();

    float2 acc[NPW];
#pragma unroll
    for (int r = 0; r < NPW; r++) acc[r] = make_float2(0.f, 0.f);
#pragma unroll 4
    for (int d2 = 0; d2 < 32; d2++) {
        float2 wn0 = sWn2[(2 * d2) * 32 + lane];
        float2 wn1 = sWn2[(2 * d2 + 1) * 32 + lane];
#pragma unroll
        for (int r = 0; r < NPW; r++) {
            float2 sa = ((const float2*)rowA[wid][r])[d2];
            acc[r].x += sa.x * wn0.x + sa.y * wn1.x;
            acc[r].y += sa.x * wn0.y + sa.y * wn1.y;
        }
    }

#pragma unroll
    for (int nd = 0; nd < NPW; nd++) {
        int node = nodeBase + nd;
        if (node >= n) break;
        float rsn = drMy[node].y;
        float c = wgt * (1.f / 3.f);
        float2 ro;
        ro.x = lk(acc[nd].x * rsn) * c;
        ro.y = lk(acc[nd].y * rsn) * c;
        atomicAdd((float2*)(outp + (size_t)node * DC + lane * 2), ro);
    }
}

// ---------------- host orchestration ---------------------------------------
extern "C" void kernel_launch(void* const* d_in, const int* in_sizes, int n_in,
                              void* d_out, int out_size) {
    const float* user_emb = (const float*)d_in[0];
    const float* item_emb = (const float*)d_in[1];
    const float* e0 = (const float*)d_in[2];
    const float* e1 = (const float*)d_in[3];
    const float* e2 = (const float*)d_in[4];
    const float* nodeW = (const float*)d_in[5];
    const float* edgeW = (const float*)d_in[6];
    const int* Ua[3] = {(const int*)d_in[7], (const int*)d_in[9], (const int*)d_in[11]};
    const int* Va[3] = {(const int*)d_in[8], (const int*)d_in[10], (const int*)d_in[12]};
    float* out = (float*)d_out;
    float* outS = out;
    float* outD = out + (size_t)NUC * DC;

    float *srcB, *dstB, *se, *de;
    int *cntU, *cntV, *rowU, *rowV, *curU, *curV;
    float2 *drU, *drV;
    int2 *adjU, *adjV;
    cudaGetSymbolAddress((void**)&srcB, g_srcB);
    cudaGetSymbolAddress((void**)&dstB, g_dstB);
    cudaGetSymbolAddress((void**)&se, g_se);
    cudaGetSymbolAddress((void**)&de, g_de);
    cudaGetSymbolAddress((void**)&cntU, g_cntU);
    cudaGetSymbolAddress((void**)&cntV, g_cntV);
    cudaGetSymbolAddress((void**)&rowU, g_rowU);
    cudaGetSymbolAddress((void**)&rowV, g_rowV);
    cudaGetSymbolAddress((void**)&curU, g_curU);
    cudaGetSymbolAddress((void**)&curV, g_curV);
    cudaGetSymbolAddress((void**)&drU, g_drU);
    cudaGetSymbolAddress((void**)&drV, g_drV);
    cudaGetSymbolAddress((void**)&adjU, g_adjU);
    cudaGetSymbolAddress((void**)&adjV, g_adjV);

    const int Ecnt[3] = {EBC, ECC, EPC};
    const float Asc = 0.0045f;
    const float* Wn0 = nodeW;
    const float* Wn1 = nodeW + (size_t)DC * DC;
    const float* We0 = edgeW;
    const int L0_SMEM = 64 * 1024;   // 2x16KB weights + 2x16KB row staging

    static int attrDone = 0;
    if (!attrDone) {
        cudaFuncSetAttribute(k_l0, cudaFuncAttributeMaxDynamicSharedMemorySize, L0_SMEM);
        attrDone = 1;
    }

    // output accumulator init (pre-scaled by 1/3) + zero nxt buffers
    k_init<<<(NUC * DC / 4 + 255) / 256, 256>>>((const float4*)user_emb,
                                                Asc / 3.f, (float4*)outS, NUC * DC / 4);
    k_init<<<(NIC * DC / 4 + 255) / 256, 256>>>((const float4*)item_emb,
                                                Asc / 3.f, (float4*)outD, NIC * DC / 4);
    cudaMemsetAsync(srcB, 0, (size_t)NUC * DC * sizeof(float));
    cudaMemsetAsync(dstB, 0, (size_t)NIC * DC * sizeof(float));

    // CSR build
    cudaMemsetAsync(cntU, 0, 3 * NUC * sizeof(int));
    cudaMemsetAsync(cntV, 0, 3 * NIC * sizeof(int));
    for (int t = 0; t < 3; t++)
        k_hist<<<(Ecnt[t] + 255) / 256, 256>>>(Ua[t], Va[t], Ecnt[t],
                                               cntU + t * NUC, cntV + t * NIC);
    k_deg<<<(3 * NUC + 255) / 256, 256>>>(cntU, drU, 3 * NUC);
    k_deg<<<(3 * NIC + 255) / 256, 256>>>(cntV, drV, 3 * NIC);
    k_scan6<<<6, 1024>>>(cntU, cntV, rowU, rowV, curU, curV);
    {
        size_t eo = 0;
        for (int t = 0; t < 3; t++) {
            k_fill<<<(Ecnt[t] + 255) / 256, 256>>>(Ua[t], Va[t], Ecnt[t],
                                                   curU + t * NUC, curV + t * NIC,
                                                   adjU + eo, adjV + eo);
            eo += Ecnt[t];
        }
    }

    // layer 0 (3 types concurrent via gridDim.y)
    {
        dim3 gu((NUC + WPB * NPW - 1) / (WPB * NPW), 3);
        dim3 gv((NIC + WPB * NPW - 1) / (WPB * NPW), 3);
        k_l0<<<gu, WPB * 32, L0_SMEM>>>(e0, e1, e2, adjU, rowU, NUC + 1,
                                        item_emb, Asc, drV, NIC, drU,
                                        Wn0, We0, srcB, se, outS, NUC);
        k_l0<<<gv, WPB * 32, L0_SMEM>>>(e0, e1, e2, adjV, rowV, NIC + 1,
                                        user_emb, Asc, drU, NUC, drV,
                                        Wn0, We0, dstB, de, outD, NIC);
    }

    // layer 1 (edge features recomputed on the fly; output accumulate only)
    {
        dim3 gu((NUC + WPB * NPW - 1) / (WPB * NPW), 3);
        dim3 gv((NIC + WPB * NPW - 1) / (WPB * NPW), 3);
        k_l1<<<gu, WPB * 32>>>(adjU, rowU, NUC + 1, se, de, drU, drV,
                               dstB, NIC, Wn1, outS, NUC);
        k_l1<<<gv, WPB * 32>>>(adjV, rowV, NIC + 1, de, se, drV, drU,
                               srcB, NUC, Wn1, outD, NIC);
    }
}